// round 1
// baseline (speedup 1.0000x reference)
#include <cuda_runtime.h>
#include <math.h>

// MoE router: logits = x[T,H] @ W[E,H]^T (fp32), top-2 -> softmax(selected)
// -> dense probs [T,E] and routing map [T,E] (written as 0.0/1.0 floats).
// Output layout assumed: d_out[0 .. T*E)        = probs (float32)
//                        d_out[T*E .. 2*T*E)    = routing_map as float
// (map writes guarded by out_size).

#define HID 4096
#define NE 64
#define TM 32
#define KC 32
#define NTHREADS 64

__global__ __launch_bounds__(NTHREADS) void moe_router_kernel(
    const float* __restrict__ x, const float* __restrict__ w,
    float* __restrict__ out, int T, int write_map)
{
    // xs: [TM][KC] row-major, stride 32 floats (LDS.128 reads are per-row
    //     broadcast within each 8-thread phase -> conflict-free).
    // ws: [NE][KC] with per-row XOR swizzle of the float4 slot:
    //     slot' = k4 ^ (e & 7). Thread eg reads experts e = eg + 8j, so its
    //     slot is (k4 ^ eg); across a phase (eg = 0..7) banks are 4*perm(0..7)
    //     -> disjoint 4-bank spans -> conflict-free for both store and load.
    __shared__ float xs[TM * KC];
    __shared__ float ws[NE * KC];
    __shared__ float lg[TM * (NE + 1)];   // stride 65 -> conflict-free scan
    __shared__ float s_p1[TM], s_p2[TM];
    __shared__ int   s_i1[TM], s_i2[TM];

    const int tid = threadIdx.x;
    const int tg = tid >> 3;   // token group 0..7 (4 tokens each)
    const int eg = tid & 7;    // expert lane 0..7 (experts eg + 8j)
    const int tok0 = blockIdx.x * TM;

    float acc[4][8];
#pragma unroll
    for (int i = 0; i < 4; i++)
#pragma unroll
        for (int j = 0; j < 8; j++) acc[i][j] = 0.f;

    const float* xbase = x + (size_t)tok0 * HID;

    for (int k0 = 0; k0 < HID; k0 += KC) {
        // ---- load x chunk: 32 tokens x 32 k (4 float4 per thread, coalesced)
#pragma unroll
        for (int q = 0; q < 4; q++) {
            int m = q * NTHREADS + tid;
            int t = m >> 3, k4 = m & 7;
            float4 v = *(const float4*)(xbase + (size_t)t * HID + k0 + k4 * 4);
            *(float4*)(xs + t * KC + k4 * 4) = v;
        }
        // ---- load W chunk: 64 experts x 32 k (8 float4 per thread, coalesced)
#pragma unroll
        for (int q = 0; q < 8; q++) {
            int m = q * NTHREADS + tid;
            int e = m >> 3, k4 = m & 7;
            float4 v = *(const float4*)(w + (size_t)e * HID + k0 + k4 * 4);
            *(float4*)(ws + e * KC + ((k4 ^ (e & 7)) << 2)) = v;
        }
        __syncthreads();

        // ---- compute: per k4 step, 4 x-vec + 8 w-vec LDS.128, 128 FFMA
#pragma unroll
        for (int k4 = 0; k4 < 8; k4++) {
            float4 xv[4];
#pragma unroll
            for (int i = 0; i < 4; i++)
                xv[i] = *(const float4*)(xs + (tg * 4 + i) * KC + k4 * 4);
            const int slot = ((k4 ^ eg) << 2);
            float4 wv[8];
#pragma unroll
            for (int j = 0; j < 8; j++)
                wv[j] = *(const float4*)(ws + (eg + 8 * j) * KC + slot);
#pragma unroll
            for (int i = 0; i < 4; i++)
#pragma unroll
                for (int j = 0; j < 8; j++) {
                    acc[i][j] = fmaf(xv[i].x, wv[j].x, acc[i][j]);
                    acc[i][j] = fmaf(xv[i].y, wv[j].y, acc[i][j]);
                    acc[i][j] = fmaf(xv[i].z, wv[j].z, acc[i][j]);
                    acc[i][j] = fmaf(xv[i].w, wv[j].w, acc[i][j]);
                }
        }
        __syncthreads();
    }

    // ---- stash logits tile to smem
#pragma unroll
    for (int i = 0; i < 4; i++)
#pragma unroll
        for (int j = 0; j < 8; j++)
            lg[(tg * 4 + i) * (NE + 1) + eg + 8 * j] = acc[i][j];
    __syncthreads();

    // ---- top-2 + softmax over the selected pair (one thread per token).
    // Ascending scan with strict '>' reproduces jax top_k tie-breaking
    // (earlier index wins on exact ties).
    if (tid < TM) {
        const float* row = lg + tid * (NE + 1);
        float v1 = -3.402823466e38f, v2 = -3.402823466e38f;
        int i1 = 0, i2 = 0;
        for (int e = 0; e < NE; e++) {
            float v = row[e];
            if (v > v1) { v2 = v1; i2 = i1; v1 = v; i1 = e; }
            else if (v > v2) { v2 = v; i2 = e; }
        }
        float ex = expf(v2 - v1);        // <= 1, stable
        float inv = 1.f / (1.f + ex);
        s_p1[tid] = inv;                  // softmax([v1,v2])[0]
        s_p2[tid] = ex * inv;             // softmax([v1,v2])[1]
        s_i1[tid] = i1;
        s_i2[tid] = i2;
    }
    __syncthreads();

    // ---- coalesced dense output: 64 threads cover one token row per iter.
    float* probs = out;
    float* rmap  = out + (size_t)T * NE;
#pragma unroll 4
    for (int r = 0; r < TM; r++) {
        int tt = tok0 + r;
        int i1 = s_i1[r], i2 = s_i2[r];
        float pv = (tid == i1) ? s_p1[r] : ((tid == i2) ? s_p2[r] : 0.f);
        probs[(size_t)tt * NE + tid] = pv;
        if (write_map)
            rmap[(size_t)tt * NE + tid] = (tid == i1 || tid == i2) ? 1.f : 0.f;
    }
}

extern "C" void kernel_launch(void* const* d_in, const int* in_sizes, int n_in,
                              void* d_out, int out_size) {
    const float* x = (const float*)d_in[0];   // hidden_states [2048,4,4096] fp32
    const float* w = (const float*)d_in[1];   // router_weight [64,4096] fp32
    float* out = (float*)d_out;
    int T = in_sizes[0] / HID;                // 8192 tokens
    int write_map = (out_size >= 2 * T * NE) ? 1 : 0;
    moe_router_kernel<<<T / TM, NTHREADS>>>(x, w, out, T, write_map);
}

// round 2
// speedup vs baseline: 1.2136x; 1.2136x over previous
#include <cuda_runtime.h>
#include <math.h>

// MoE router: logits = x[T,4096] @ W[64,4096]^T (fp32 via packed f32x2 FFMA2),
// top-2 -> softmax(selected) -> dense probs [T,64] + routing map (0/1 floats).
// Out layout: [0..T*64) probs, [T*64..2*T*64) map (guarded by out_size).

#define HID 4096
#define NE 64
#define TM 32          // tokens per CTA
#define KC 32          // k-chunk (floats)
#define NT 128         // threads per CTA
#define XSTR 36        // xs row stride (floats): 16B-aligned rows, conflict-free bcast

typedef unsigned long long u64t;

__device__ __forceinline__ unsigned smem_u32(const void* p) {
    unsigned r;
    asm("{ .reg .u64 t; cvta.to.shared.u64 t, %1; cvt.u32.u64 %0, t; }"
        : "=r"(r) : "l"(p));
    return r;
}
__device__ __forceinline__ void lds_v2u64(u64t& a, u64t& b, unsigned addr) {
    asm volatile("ld.shared.v2.u64 {%0,%1},[%2];" : "=l"(a), "=l"(b) : "r"(addr));
}
__device__ __forceinline__ void ffma2(u64t& d, u64t a, u64t b) {
    asm volatile("fma.rn.f32x2 %0,%1,%2,%0;" : "+l"(d) : "l"(a), "l"(b));
}
__device__ __forceinline__ float unpack_sum(u64t v) {
    float lo, hi;
    asm("mov.b64 {%0,%1},%2;" : "=f"(lo), "=f"(hi) : "l"(v));
    return lo + hi;
}
#define CP16(dst, src) asm volatile("cp.async.cg.shared.global [%0],[%1],16;" :: "r"(dst), "l"(src))
#define CPCOMMIT()     asm volatile("cp.async.commit_group;")
#define CPWAIT1()      asm volatile("cp.async.wait_group 1;")

__global__ __launch_bounds__(NT) void moe_router_kernel(
    const float* __restrict__ x, const float* __restrict__ w,
    float* __restrict__ out, int T, int write_map)
{
    __shared__ float xs[2][TM * XSTR];       // x chunk, double buffered
    __shared__ float ws[2][NE * KC];         // W chunk, XOR-swizzled
    __shared__ float lg[TM * (NE + 1)];      // logits tile (stride 65)
    __shared__ float s_p1[TM], s_p2[TM];
    __shared__ int   s_i1[TM], s_i2[TM];

    const int tid = threadIdx.x;
    const int tg = tid >> 3;                 // token group 0..15 (2 tokens each)
    const int eg = tid & 7;                  // expert lane 0..7
    const int tok0 = blockIdx.x * TM;
    const float* xbase = x + (size_t)tok0 * HID;

    const unsigned xs_b = smem_u32(xs);
    const unsigned ws_b = smem_u32(ws);
    const unsigned XBUF = TM * XSTR * 4;     // bytes per xs buffer
    const unsigned WBUF = NE * KC * 4;

    // precomputed cp.async targets (chunk-invariant parts)
    // x: 2 float4 per thread; w: 4 float4 per thread
    int xm0 = tid, xm1 = NT + tid;
    int xt0 = xm0 >> 3, xk0 = xm0 & 7, xt1 = xm1 >> 3, xk1 = xm1 & 7;
    unsigned xd0 = xs_b + (unsigned)(xt0 * XSTR + xk0 * 4) * 4;
    unsigned xd1 = xs_b + (unsigned)(xt1 * XSTR + xk1 * 4) * 4;
    const float* xsrc0 = xbase + (size_t)xt0 * HID + xk0 * 4;
    const float* xsrc1 = xbase + (size_t)xt1 * HID + xk1 * 4;

    unsigned wdst[4]; const float* wsrc[4];
#pragma unroll
    for (int q = 0; q < 4; q++) {
        int m = q * NT + tid, e = m >> 3, k4 = m & 7;
        wdst[q] = ws_b + (unsigned)(e * KC + ((k4 ^ (e & 7)) << 2)) * 4;
        wsrc[q] = w + (size_t)e * HID + k4 * 4;
    }

    u64t acc[2][8];
#pragma unroll
    for (int i = 0; i < 2; i++)
#pragma unroll
        for (int j = 0; j < 8; j++) acc[i][j] = 0ull;

    // issue chunk 0 into buffer 0
    CP16(xd0, xsrc0); CP16(xd1, xsrc1);
#pragma unroll
    for (int q = 0; q < 4; q++) CP16(wdst[q], wsrc[q]);
    CPCOMMIT();

    const unsigned xrow0 = xs_b + (unsigned)((tg * 2 + 0) * XSTR) * 4;
    const unsigned xrow1 = xs_b + (unsigned)((tg * 2 + 1) * XSTR) * 4;

    const int NCH = HID / KC;                // 128 chunks
    for (int c = 0; c < NCH; c++) {
        // prefetch chunk c+1 into the other buffer
        if (c + 1 < NCH) {
            unsigned boff = ((c + 1) & 1) ? XBUF : 0;
            unsigned woff = ((c + 1) & 1) ? WBUF : 0;
            int k0 = (c + 1) * KC;
            CP16(xd0 + boff, xsrc0 + k0);
            CP16(xd1 + boff, xsrc1 + k0);
#pragma unroll
            for (int q = 0; q < 4; q++) CP16(wdst[q] + woff, wsrc[q] + k0);
        }
        CPCOMMIT();
        CPWAIT1();              // chunk c's copies landed (this thread)
        __syncthreads();        // visible to all threads

        const unsigned xo = (c & 1) ? XBUF : 0;
        const unsigned wo = (c & 1) ? WBUF : 0;
#pragma unroll
        for (int k4 = 0; k4 < 8; k4++) {
            u64t x0a, x0b, x1a, x1b;
            lds_v2u64(x0a, x0b, xrow0 + xo + k4 * 16);
            lds_v2u64(x1a, x1b, xrow1 + xo + k4 * 16);
            const unsigned slot = ((unsigned)(k4 ^ eg)) * 16;
            u64t wa[8], wb[8];
#pragma unroll
            for (int j = 0; j < 8; j++)
                lds_v2u64(wa[j], wb[j],
                          ws_b + wo + (unsigned)((eg + 8 * j) * KC) * 4 + slot);
#pragma unroll
            for (int j = 0; j < 8; j++) {
                ffma2(acc[0][j], x0a, wa[j]);
                ffma2(acc[0][j], x0b, wb[j]);
                ffma2(acc[1][j], x1a, wa[j]);
                ffma2(acc[1][j], x1b, wb[j]);
            }
        }
        __syncthreads();        // compute done before buffer c&1 is re-filled
    }

    // ---- logits tile to smem
#pragma unroll
    for (int i = 0; i < 2; i++)
#pragma unroll
        for (int j = 0; j < 8; j++)
            lg[(tg * 2 + i) * (NE + 1) + eg + 8 * j] = unpack_sum(acc[i][j]);
    __syncthreads();

    // ---- top-2 + softmax over selected (one thread per token).
    // Ascending scan, strict '>' matches jax top_k tie-break (earlier idx wins).
    if (tid < TM) {
        const float* row = lg + tid * (NE + 1);
        float v1 = -3.402823466e38f, v2 = -3.402823466e38f;
        int i1 = 0, i2 = 0;
#pragma unroll 4
        for (int e = 0; e < NE; e++) {
            float v = row[e];
            if (v > v1) { v2 = v1; i2 = i1; v1 = v; i1 = e; }
            else if (v > v2) { v2 = v; i2 = e; }
        }
        float ex = __expf(v2 - v1) ;      // use fast exp? keep accurate:
        ex = expf(v2 - v1);               // <= 1, stable
        float inv = 1.f / (1.f + ex);
        s_p1[tid] = inv;
        s_p2[tid] = ex * inv;
        s_i1[tid] = i1;
        s_i2[tid] = i2;
    }
    __syncthreads();

    // ---- dense output, coalesced: 128 threads = 2 token rows per iter
    float* probs = out;
    float* rmap  = out + (size_t)T * NE;
    const int r0 = tid >> 6;              // 0..1
    const int col = tid & 63;
#pragma unroll 4
    for (int rr = 0; rr < TM / 2; rr++) {
        int r = rr * 2 + r0;
        int tt = tok0 + r;
        int i1 = s_i1[r], i2 = s_i2[r];
        float pv = (col == i1) ? s_p1[r] : ((col == i2) ? s_p2[r] : 0.f);
        probs[(size_t)tt * NE + col] = pv;
        if (write_map)
            rmap[(size_t)tt * NE + col] = (col == i1 || col == i2) ? 1.f : 0.f;
    }
}

extern "C" void kernel_launch(void* const* d_in, const int* in_sizes, int n_in,
                              void* d_out, int out_size) {
    const float* x = (const float*)d_in[0];   // [2048,4,4096] fp32
    const float* w = (const float*)d_in[1];   // [64,4096] fp32
    float* out = (float*)d_out;
    int T = in_sizes[0] / HID;                // 8192
    int write_map = (out_size >= 2 * T * NE) ? 1 : 0;
    moe_router_kernel<<<T / TM, NT>>>(x, w, out, T, write_map);
}

// round 4
// speedup vs baseline: 2.1639x; 1.7830x over previous
#include <cuda_runtime.h>
#include <math.h>

// MoE router via mma.sync (tf32, 2-plane split, 3 products — fp32-faithful):
//   logits = x[T,4096] @ W[64,4096]^T
//   x = xh + xm (tf32 planes, exact residual); W likewise (presplit kernel).
//   acc += xh*Wh + xh*Wm + xm*Wh   (fp32 accumulators; dropped xm*Wm ~2^-44)
// K1: W -> tf32 planes (fp32 storage).  K2: split-K(2) GEMM -> fp32 partials.
// K3: reduce + top-2 (jax tie-break) + softmax -> dense probs + routing map.

#define HID  4096
#define NE   64
#define TM   128                  // tokens per CTA
#define KC   32                   // K chunk
#define KSPL 2
#define KPER (HID / KSPL)         // 2048
#define NCH  (KPER / KC)          // 64
#define NT   256

// dynamic smem offsets (floats), row stride 36 (conflict-free everywhere)
#define AH 0
#define AM (128 * 36)             // 4608
#define BH (2 * 128 * 36)         // 9216
#define BM (BH + 64 * 36)         // 11520
#define SMEM_FLOATS (BM + 64 * 36)
#define SMEM_BYTES (SMEM_FLOATS * 4)   // 55296

static __device__ float g_wh[NE * HID];
static __device__ float g_wm[NE * HID];
static __device__ float g_partial[KSPL * 8192 * NE];

__device__ __forceinline__ unsigned tf32_rna(float v) {
    unsigned r;
    asm("cvt.rna.tf32.f32 %0, %1;" : "=r"(r) : "f"(v));
    return r;
}
__device__ __forceinline__ void mma_tf32(float* c, const unsigned* a, const unsigned* b) {
    asm volatile(
        "mma.sync.aligned.m16n8k8.row.col.f32.tf32.tf32.f32 "
        "{%0,%1,%2,%3},{%4,%5,%6,%7},{%8,%9},{%0,%1,%2,%3};"
        : "+f"(c[0]), "+f"(c[1]), "+f"(c[2]), "+f"(c[3])
        : "r"(a[0]), "r"(a[1]), "r"(a[2]), "r"(a[3]), "r"(b[0]), "r"(b[1]));
}

// ---------------- kernel 1: W -> tf32 planes ----------------
__global__ __launch_bounds__(256) void wsplit_kernel(const float* __restrict__ w) {
    int idx = blockIdx.x * 256 + threadIdx.x;          // float4 index
    float4 v = ((const float4*)w)[idx];
    float4 h, m;
    h.x = __uint_as_float(tf32_rna(v.x)); m.x = __uint_as_float(tf32_rna(v.x - h.x));
    h.y = __uint_as_float(tf32_rna(v.y)); m.y = __uint_as_float(tf32_rna(v.y - h.y));
    h.z = __uint_as_float(tf32_rna(v.z)); m.z = __uint_as_float(tf32_rna(v.z - h.z));
    h.w = __uint_as_float(tf32_rna(v.w)); m.w = __uint_as_float(tf32_rna(v.w - h.w));
    ((float4*)g_wh)[idx] = h;
    ((float4*)g_wm)[idx] = m;
}

// ---------------- kernel 2: split-K GEMM ----------------
__global__ __launch_bounds__(NT) void moe_gemm_kernel(const float* __restrict__ x, int T) {
    extern __shared__ float sm[];
    const int tid = threadIdx.x;
    const int wid = tid >> 5;
    const int lane = tid & 31;
    const int tok0 = blockIdx.x * TM;
    const int ks = blockIdx.y;
    const int kbase = ks * KPER;

    // ---- chunk-invariant addressing
    // x: 4 float4/thread; u = it*256+tid -> row=u>>3, c4=u&7
    const float4* px[4]; unsigned sax[4];
    #pragma unroll
    for (int it = 0; it < 4; it++) {
        int u = it * 256 + tid, row = u >> 3, c4 = u & 7;
        px[it] = (const float4*)(x + (size_t)(tok0 + row) * HID + kbase + c4 * 4);
        sax[it] = row * 36 + c4 * 4;
    }
    // W: 2 float4/thread per plane; u = q*256+tid -> row=u>>3, c4=u&7
    const float4* pwh[2]; const float4* pwm[2]; unsigned saw[2];
    #pragma unroll
    for (int q = 0; q < 2; q++) {
        int u = q * 256 + tid, row = u >> 3, c4 = u & 7;
        pwh[q] = (const float4*)(g_wh + (size_t)row * HID + kbase + c4 * 4);
        pwm[q] = (const float4*)(g_wm + (size_t)row * HID + kbase + c4 * 4);
        saw[q] = row * 36 + c4 * 4;
    }

    float acc[8][4];
    #pragma unroll
    for (int n = 0; n < 8; n++)
        #pragma unroll
        for (int i = 0; i < 4; i++) acc[n][i] = 0.f;

    // prefetch chunk 0
    float4 rxv[4], rwh[2], rwm[2];
    #pragma unroll
    for (int it = 0; it < 4; it++) rxv[it] = px[it][0];
    #pragma unroll
    for (int q = 0; q < 2; q++) { rwh[q] = pwh[q][0]; rwm[q] = pwm[q][0]; }

    const int wr = wid * 16;
    const int r0 = wr + (lane >> 2);
    const int eq = lane >> 2;
    const int kq = lane & 3;

    #pragma unroll 1
    for (int c = 0; c < NCH; c++) {
        __syncthreads();                 // previous compute done, smem reusable
        // stage x (convert to planes) and W
        #pragma unroll
        for (int it = 0; it < 4; it++) {
            float4 v = rxv[it], h, m;
            h.x = __uint_as_float(tf32_rna(v.x)); m.x = __uint_as_float(tf32_rna(v.x - h.x));
            h.y = __uint_as_float(tf32_rna(v.y)); m.y = __uint_as_float(tf32_rna(v.y - h.y));
            h.z = __uint_as_float(tf32_rna(v.z)); m.z = __uint_as_float(tf32_rna(v.z - h.z));
            h.w = __uint_as_float(tf32_rna(v.w)); m.w = __uint_as_float(tf32_rna(v.w - h.w));
            *(float4*)(sm + AH + sax[it]) = h;
            *(float4*)(sm + AM + sax[it]) = m;
        }
        #pragma unroll
        for (int q = 0; q < 2; q++) {
            *(float4*)(sm + BH + saw[q]) = rwh[q];
            *(float4*)(sm + BM + saw[q]) = rwm[q];
        }
        // prefetch chunk c+1 (overlaps compute below)
        if (c + 1 < NCH) {
            const int f4 = (c + 1) * (KC / 4);
            #pragma unroll
            for (int it = 0; it < 4; it++) rxv[it] = px[it][f4];
            #pragma unroll
            for (int q = 0; q < 2; q++) { rwh[q] = pwh[q][f4]; rwm[q] = pwm[q][f4]; }
        }
        __syncthreads();

        #pragma unroll
        for (int s = 0; s < 4; s++) {
            const int kl = s * 8 + kq;
            unsigned Ah[4], Am[4];
            Ah[0] = __float_as_uint(sm[AH + r0 * 36 + kl]);
            Ah[1] = __float_as_uint(sm[AH + (r0 + 8) * 36 + kl]);
            Ah[2] = __float_as_uint(sm[AH + r0 * 36 + kl + 4]);
            Ah[3] = __float_as_uint(sm[AH + (r0 + 8) * 36 + kl + 4]);
            Am[0] = __float_as_uint(sm[AM + r0 * 36 + kl]);
            Am[1] = __float_as_uint(sm[AM + (r0 + 8) * 36 + kl]);
            Am[2] = __float_as_uint(sm[AM + r0 * 36 + kl + 4]);
            Am[3] = __float_as_uint(sm[AM + (r0 + 8) * 36 + kl + 4]);
            unsigned Bh[8][2], Bm[8][2];
            #pragma unroll
            for (int nt = 0; nt < 8; nt++) {
                int e = nt * 8 + eq;
                Bh[nt][0] = __float_as_uint(sm[BH + e * 36 + kl]);
                Bh[nt][1] = __float_as_uint(sm[BH + e * 36 + kl + 4]);
                Bm[nt][0] = __float_as_uint(sm[BM + e * 36 + kl]);
                Bm[nt][1] = __float_as_uint(sm[BM + e * 36 + kl + 4]);
            }
            #pragma unroll
            for (int nt = 0; nt < 8; nt++) mma_tf32(acc[nt], Ah, Bh[nt]);
            #pragma unroll
            for (int nt = 0; nt < 8; nt++) mma_tf32(acc[nt], Ah, Bm[nt]);
            #pragma unroll
            for (int nt = 0; nt < 8; nt++) mma_tf32(acc[nt], Am, Bh[nt]);
        }
    }

    // ---- write fp32 partials
    const int grow = tok0 + r0;
    float* dst0 = g_partial + ((size_t)ks * T + grow) * NE;
    float* dst8 = dst0 + (size_t)8 * NE;
    #pragma unroll
    for (int nt = 0; nt < 8; nt++) {
        int col = nt * 8 + kq * 2;
        *(float2*)(dst0 + col) = make_float2(acc[nt][0], acc[nt][1]);
        *(float2*)(dst8 + col) = make_float2(acc[nt][2], acc[nt][3]);
    }
}

// ---------------- kernel 3: reduce + top-2 + softmax ----------------
__global__ __launch_bounds__(256) void moe_top2_kernel(float* __restrict__ out,
                                                       int T, int write_map) {
    const int lane = threadIdx.x & 31;
    const int t = blockIdx.x * 8 + (threadIdx.x >> 5);
    const float* p0 = g_partial + (size_t)t * NE;
    const float* p1 = g_partial + ((size_t)T + t) * NE;
    float a = p0[lane] + p1[lane];
    float bv = p0[lane + 32] + p1[lane + 32];

    float v1, v2; int i1, i2;
    if (bv > a) { v1 = bv; i1 = lane + 32; v2 = a; i2 = lane; }
    else        { v1 = a;  i1 = lane;      v2 = bv; i2 = lane + 32; }

    #pragma unroll
    for (int s = 16; s >= 1; s >>= 1) {
        float ov1 = __shfl_xor_sync(0xffffffffu, v1, s);
        int   oi1 = __shfl_xor_sync(0xffffffffu, i1, s);
        float ov2 = __shfl_xor_sync(0xffffffffu, v2, s);
        int   oi2 = __shfl_xor_sync(0xffffffffu, i2, s);
        bool ob = (ov1 > v1) || (ov1 == v1 && oi1 < i1);   // jax tie-break
        float nv1 = ob ? ov1 : v1;  int ni1 = ob ? oi1 : i1;
        float cv  = ob ? v1  : ov1; int ci  = ob ? i1  : oi1;
        float sv  = ob ? ov2 : v2;  int si  = ob ? oi2 : i2;
        bool b2 = (cv > sv) || (cv == sv && ci < si);
        v2 = b2 ? cv : sv; i2 = b2 ? ci : si;
        v1 = nv1; i1 = ni1;
    }
    float ex = expf(v2 - v1);            // <= 1, stable
    float inv = 1.f / (1.f + ex);
    float pp1 = inv, pp2 = ex * inv;

    float* probs = out + (size_t)t * NE;
    probs[lane]      = (lane == i1) ? pp1 : ((lane == i2) ? pp2 : 0.f);
    probs[lane + 32] = (lane + 32 == i1) ? pp1 : ((lane + 32 == i2) ? pp2 : 0.f);
    if (write_map) {
        float* rmap = out + (size_t)T * NE + (size_t)t * NE;
        rmap[lane]      = (lane == i1 || lane == i2) ? 1.f : 0.f;
        rmap[lane + 32] = (lane + 32 == i1 || lane + 32 == i2) ? 1.f : 0.f;
    }
}

extern "C" void kernel_launch(void* const* d_in, const int* in_sizes, int n_in,
                              void* d_out, int out_size) {
    const float* x = (const float*)d_in[0];   // [2048,4,4096] fp32
    const float* w = (const float*)d_in[1];   // [64,4096] fp32
    float* out = (float*)d_out;
    int T = in_sizes[0] / HID;                // 8192
    int write_map = (out_size >= 2 * T * NE) ? 1 : 0;

    static int smem_set = 0;
    if (!smem_set) {
        cudaFuncSetAttribute(moe_gemm_kernel,
                             cudaFuncAttributeMaxDynamicSharedMemorySize, SMEM_BYTES);
        smem_set = 1;
    }
    wsplit_kernel<<<(NE * HID / 4) / 256, 256>>>(w);
    dim3 grid(T / TM, KSPL);
    moe_gemm_kernel<<<grid, NT, SMEM_BYTES>>>(x, T);
    moe_top2_kernel<<<T / 8, 256>>>(out, T, write_map);
}

// round 5
// speedup vs baseline: 2.2838x; 1.0554x over previous
#include <cuda_runtime.h>
#include <math.h>

// MoE router via mma.sync tf32 2-plane split (3 products, fp32-faithful).
// R5: raw-fp32 smem staging via cp.async (3-stage), tf32 split at fragment
// load, M_w=32 per warp, TM=256, split-K=4. No W-presplit kernel.

#define HID  4096
#define NE   64
#define TM   256
#define KC   32
#define KSPL 4
#define KPER (HID / KSPL)         // 1024
#define NCH  (KPER / KC)          // 32
#define NT   256
#define STAGES 3
#define XSTR 36                   // row stride (floats) -> conflict-free frags
#define XOFF 0
#define WOFF (TM * XSTR)          // 9216 floats
#define STG_FLOATS (TM * XSTR + NE * XSTR)   // 11520
#define SMEM_BYTES (STAGES * STG_FLOATS * 4) // 138240

static __device__ float g_partial[KSPL * 8192 * NE];   // 8 MB

__device__ __forceinline__ unsigned smem_u32(const void* p) {
    unsigned r;
    asm("{ .reg .u64 t; cvta.to.shared.u64 t, %1; cvt.u32.u64 %0, t; }"
        : "=r"(r) : "l"(p));
    return r;
}
__device__ __forceinline__ unsigned tf32_rna(float v) {
    unsigned r;
    asm("cvt.rna.tf32.f32 %0, %1;" : "=r"(r) : "f"(v));
    return r;
}
__device__ __forceinline__ void split1(float v, unsigned& h, unsigned& m) {
    h = tf32_rna(v);
    m = tf32_rna(v - __uint_as_float(h));
}
__device__ __forceinline__ void mma_tf32(float* c, const unsigned* a, const unsigned* b) {
    asm volatile(
        "mma.sync.aligned.m16n8k8.row.col.f32.tf32.tf32.f32 "
        "{%0,%1,%2,%3},{%4,%5,%6,%7},{%8,%9},{%0,%1,%2,%3};"
        : "+f"(c[0]), "+f"(c[1]), "+f"(c[2]), "+f"(c[3])
        : "r"(a[0]), "r"(a[1]), "r"(a[2]), "r"(a[3]), "r"(b[0]), "r"(b[1]));
}
#define CP16(dst, src) asm volatile("cp.async.cg.shared.global [%0],[%1],16;" :: "r"(dst), "l"(src))
#define CPCOMMIT()     asm volatile("cp.async.commit_group;")
#define CPWAIT2()      asm volatile("cp.async.wait_group %0;" :: "n"(STAGES - 1))

// ---------------- GEMM: split-K(4), fp32 partials ----------------
__global__ __launch_bounds__(NT) void moe_gemm_kernel(
    const float* __restrict__ x, const float* __restrict__ w, int T)
{
    extern __shared__ float sm[];
    const unsigned sbase = smem_u32(sm);
    const int tid = threadIdx.x;
    const int wid = tid >> 5;
    const int lane = tid & 31;
    const int tok0 = blockIdx.x * TM;
    const int ks = blockIdx.y;
    const int kbase = ks * KPER;

    // cp.async source/dst mapping (chunk-invariant parts)
    // x: 8 segs of 16B per thread; u = it*NT+tid -> row=u>>3, c4=u&7
    const float* xsrc[8]; unsigned xdst[8];
    #pragma unroll
    for (int it = 0; it < 8; it++) {
        int u = it * NT + tid, row = u >> 3, c4 = u & 7;
        xsrc[it] = x + (size_t)(tok0 + row) * HID + kbase + c4 * 4;
        xdst[it] = sbase + (unsigned)(XOFF + row * XSTR + c4 * 4) * 4;
    }
    // W: 2 segs per thread
    const float* wsrc[2]; unsigned wdst[2];
    #pragma unroll
    for (int q = 0; q < 2; q++) {
        int u = q * NT + tid, row = u >> 3, c4 = u & 7;
        wsrc[q] = w + (size_t)row * HID + kbase + c4 * 4;
        wdst[q] = sbase + (unsigned)(WOFF + row * XSTR + c4 * 4) * 4;
    }

    float acc[2][8][4];
    #pragma unroll
    for (int mt = 0; mt < 2; mt++)
        #pragma unroll
        for (int nt = 0; nt < 8; nt++)
            #pragma unroll
            for (int i = 0; i < 4; i++) acc[mt][nt][i] = 0.f;

    // prologue: stages 0,1
    #pragma unroll
    for (int s = 0; s < 2; s++) {
        unsigned so = (unsigned)(s * STG_FLOATS) * 4;
        int ko = s * KC;
        #pragma unroll
        for (int it = 0; it < 8; it++) CP16(xdst[it] + so, xsrc[it] + ko);
        #pragma unroll
        for (int q = 0; q < 2; q++)  CP16(wdst[q] + so, wsrc[q] + ko);
        CPCOMMIT();
    }

    const int eq = lane >> 2;           // 0..7
    const int kq = lane & 3;            // 0..3
    const int rbase = wid * 32 + eq;    // A row base within tile

    #pragma unroll 1
    for (int c = 0; c < NCH; c++) {
        __syncthreads();                // all readers done with buffer (c+2)%3
        if (c + 2 < NCH) {
            unsigned so = (unsigned)(((c + 2) % STAGES) * STG_FLOATS) * 4;
            int ko = (c + 2) * KC;
            #pragma unroll
            for (int it = 0; it < 8; it++) CP16(xdst[it] + so, xsrc[it] + ko);
            #pragma unroll
            for (int q = 0; q < 2; q++)  CP16(wdst[q] + so, wsrc[q] + ko);
        }
        CPCOMMIT();
        CPWAIT2();                      // stage c landed (this thread)
        __syncthreads();                // landed for all threads

        const float* sx = sm + (c % STAGES) * STG_FLOATS;
        const float* sw = sx + WOFF;

        #pragma unroll
        for (int s = 0; s < 4; s++) {
            const int kl = s * 8 + kq;
            unsigned Ah[2][4], Am[2][4];
            #pragma unroll
            for (int mt = 0; mt < 2; mt++) {
                int r = rbase + mt * 16;
                split1(sx[r * XSTR + kl],            Ah[mt][0], Am[mt][0]);
                split1(sx[(r + 8) * XSTR + kl],      Ah[mt][1], Am[mt][1]);
                split1(sx[r * XSTR + kl + 4],        Ah[mt][2], Am[mt][2]);
                split1(sx[(r + 8) * XSTR + kl + 4],  Ah[mt][3], Am[mt][3]);
            }
            unsigned Bh[8][2], Bm[8][2];
            #pragma unroll
            for (int nt = 0; nt < 8; nt++) {
                int e = nt * 8 + eq;
                split1(sw[e * XSTR + kl],     Bh[nt][0], Bm[nt][0]);
                split1(sw[e * XSTR + kl + 4], Bh[nt][1], Bm[nt][1]);
            }
            #pragma unroll
            for (int mt = 0; mt < 2; mt++)
                #pragma unroll
                for (int nt = 0; nt < 8; nt++) {
                    mma_tf32(acc[mt][nt], Ah[mt], Bh[nt]);
                    mma_tf32(acc[mt][nt], Ah[mt], Bm[nt]);
                    mma_tf32(acc[mt][nt], Am[mt], Bh[nt]);
                }
        }
    }

    // ---- fp32 partials
    #pragma unroll
    for (int mt = 0; mt < 2; mt++) {
        int row = tok0 + rbase + mt * 16;
        float* d0 = g_partial + ((size_t)ks * T + row) * NE;
        float* d8 = d0 + (size_t)8 * NE;
        #pragma unroll
        for (int nt = 0; nt < 8; nt++) {
            int col = nt * 8 + kq * 2;
            *(float2*)(d0 + col) = make_float2(acc[mt][nt][0], acc[mt][nt][1]);
            *(float2*)(d8 + col) = make_float2(acc[mt][nt][2], acc[mt][nt][3]);
        }
    }
}

// ---------------- reduce + top-2 + softmax ----------------
__global__ __launch_bounds__(256) void moe_top2_kernel(float* __restrict__ out,
                                                       int T, int write_map) {
    const int lane = threadIdx.x & 31;
    const int t = blockIdx.x * 8 + (threadIdx.x >> 5);
    float a = 0.f, bv = 0.f;
    #pragma unroll
    for (int ksi = 0; ksi < KSPL; ksi++) {
        const float* p = g_partial + ((size_t)ksi * T + t) * NE;
        a += p[lane];
        bv += p[lane + 32];
    }

    float v1, v2; int i1, i2;
    if (bv > a) { v1 = bv; i1 = lane + 32; v2 = a; i2 = lane; }
    else        { v1 = a;  i1 = lane;      v2 = bv; i2 = lane + 32; }

    #pragma unroll
    for (int s = 16; s >= 1; s >>= 1) {
        float ov1 = __shfl_xor_sync(0xffffffffu, v1, s);
        int   oi1 = __shfl_xor_sync(0xffffffffu, i1, s);
        float ov2 = __shfl_xor_sync(0xffffffffu, v2, s);
        int   oi2 = __shfl_xor_sync(0xffffffffu, i2, s);
        bool ob = (ov1 > v1) || (ov1 == v1 && oi1 < i1);   // jax tie-break
        float nv1 = ob ? ov1 : v1;  int ni1 = ob ? oi1 : i1;
        float cv  = ob ? v1  : ov1; int ci  = ob ? i1  : oi1;
        float sv  = ob ? ov2 : v2;  int si  = ob ? oi2 : i2;
        bool b2 = (cv > sv) || (cv == sv && ci < si);
        v2 = b2 ? cv : sv; i2 = b2 ? ci : si;
        v1 = nv1; i1 = ni1;
    }
    float ex = expf(v2 - v1);            // <= 1, stable
    float inv = 1.f / (1.f + ex);
    float pp1 = inv, pp2 = ex * inv;

    float* probs = out + (size_t)t * NE;
    probs[lane]      = (lane == i1) ? pp1 : ((lane == i2) ? pp2 : 0.f);
    probs[lane + 32] = (lane + 32 == i1) ? pp1 : ((lane + 32 == i2) ? pp2 : 0.f);
    if (write_map) {
        float* rmap = out + (size_t)T * NE + (size_t)t * NE;
        rmap[lane]      = (lane == i1 || lane == i2) ? 1.f : 0.f;
        rmap[lane + 32] = (lane + 32 == i1 || lane + 32 == i2) ? 1.f : 0.f;
    }
}

extern "C" void kernel_launch(void* const* d_in, const int* in_sizes, int n_in,
                              void* d_out, int out_size) {
    const float* x = (const float*)d_in[0];   // [2048,4,4096] fp32
    const float* w = (const float*)d_in[1];   // [64,4096] fp32
    float* out = (float*)d_out;
    int T = in_sizes[0] / HID;                // 8192
    int write_map = (out_size >= 2 * T * NE) ? 1 : 0;

    static int smem_set = 0;
    if (!smem_set) {
        cudaFuncSetAttribute(moe_gemm_kernel,
                             cudaFuncAttributeMaxDynamicSharedMemorySize, SMEM_BYTES);
        smem_set = 1;
    }
    dim3 grid(T / TM, KSPL);
    moe_gemm_kernel<<<grid, NT, SMEM_BYTES>>>(x, w, T);
    moe_top2_kernel<<<T / 8, 256>>>(out, T, write_map);
}

// round 6
// speedup vs baseline: 3.2162x; 1.4083x over previous
#include <cuda_runtime.h>
#include <cuda_fp16.h>
#include <math.h>

// MoE router via mma.sync m16n8k16 fp16 2-plane split (3 products):
//   logits = x[T,4096] @ W[64,4096]^T, fp32 accumulate.
//   x = xh + xm (fp16 planes, exact residual); W*64 likewise (scale exact,
//   undone in epilogue). acc += xh*Wh + xh*Wm + xm*Wh.
// Raw fp32 staged via 3-stage cp.async; split to fp16 at fragment load.

#define HID  4096
#define NE   64
#define TM   256
#define KC   32
#define KSPL 4
#define KPER (HID / KSPL)         // 1024
#define NCH  (KPER / KC)          // 32
#define NT   256
#define STAGES 3
#define XSTR 36                   // row stride (floats) -> conflict-free frags
#define WOFF (TM * XSTR)          // 9216 floats
#define STG_FLOATS (TM * XSTR + NE * XSTR)   // 11520
#define SMEM_BYTES (STAGES * STG_FLOATS * 4) // 138240

static __device__ float g_partial[KSPL * 8192 * NE];   // 8 MB

__device__ __forceinline__ unsigned smem_u32(const void* p) {
    unsigned r;
    asm("{ .reg .u64 t; cvta.to.shared.u64 t, %1; cvt.u32.u64 %0, t; }"
        : "=r"(r) : "l"(p));
    return r;
}
// split a float2 into fp16 hi plane + exact-residual fp16 mid plane
__device__ __forceinline__ void pairsplit(const float* p, unsigned& h, unsigned& m) {
    float2 v = *(const float2*)p;
    __half2 hh = __float22half2_rn(v);
    float2 hb = __half22float2(hh);
    __half2 mm = __float22half2_rn(make_float2(v.x - hb.x, v.y - hb.y));
    h = *(unsigned*)&hh;
    m = *(unsigned*)&mm;
}
// same, with x64 pre-scale (keeps W residual plane in fp16 normal range)
__device__ __forceinline__ void pairsplitW(const float* p, unsigned& h, unsigned& m) {
    float2 v = *(const float2*)p;
    v.x *= 64.f; v.y *= 64.f;
    __half2 hh = __float22half2_rn(v);
    float2 hb = __half22float2(hh);
    __half2 mm = __float22half2_rn(make_float2(v.x - hb.x, v.y - hb.y));
    h = *(unsigned*)&hh;
    m = *(unsigned*)&mm;
}
__device__ __forceinline__ void mma_f16(float* c, const unsigned* a, const unsigned* b) {
    asm volatile(
        "mma.sync.aligned.m16n8k16.row.col.f32.f16.f16.f32 "
        "{%0,%1,%2,%3},{%4,%5,%6,%7},{%8,%9},{%0,%1,%2,%3};"
        : "+f"(c[0]), "+f"(c[1]), "+f"(c[2]), "+f"(c[3])
        : "r"(a[0]), "r"(a[1]), "r"(a[2]), "r"(a[3]), "r"(b[0]), "r"(b[1]));
}
#define CP16(dst, src) asm volatile("cp.async.cg.shared.global [%0],[%1],16;" :: "r"(dst), "l"(src))
#define CPCOMMIT()     asm volatile("cp.async.commit_group;")
#define CPWAIT2()      asm volatile("cp.async.wait_group %0;" :: "n"(STAGES - 1))

// ---------------- GEMM: split-K(4), fp32 partials ----------------
__global__ __launch_bounds__(NT) void moe_gemm_kernel(
    const float* __restrict__ x, const float* __restrict__ w, int T)
{
    extern __shared__ float sm[];
    const unsigned sbase = smem_u32(sm);
    const int tid = threadIdx.x;
    const int wid = tid >> 5;
    const int lane = tid & 31;
    const int tok0 = blockIdx.x * TM;
    const int ks = blockIdx.y;
    const int kbase = ks * KPER;

    // cp.async mapping: x 8 x 16B/thread, W 2 x 16B/thread
    const float* xsrc[8]; unsigned xdst[8];
    #pragma unroll
    for (int it = 0; it < 8; it++) {
        int u = it * NT + tid, row = u >> 3, c4 = u & 7;
        xsrc[it] = x + (size_t)(tok0 + row) * HID + kbase + c4 * 4;
        xdst[it] = sbase + (unsigned)(row * XSTR + c4 * 4) * 4;
    }
    const float* wsrc[2]; unsigned wdst[2];
    #pragma unroll
    for (int q = 0; q < 2; q++) {
        int u = q * NT + tid, row = u >> 3, c4 = u & 7;
        wsrc[q] = w + (size_t)row * HID + kbase + c4 * 4;
        wdst[q] = sbase + (unsigned)(WOFF + row * XSTR + c4 * 4) * 4;
    }

    float acc[2][8][4];
    #pragma unroll
    for (int mt = 0; mt < 2; mt++)
        #pragma unroll
        for (int nt = 0; nt < 8; nt++)
            #pragma unroll
            for (int i = 0; i < 4; i++) acc[mt][nt][i] = 0.f;

    // prologue: stages 0,1
    #pragma unroll
    for (int s = 0; s < 2; s++) {
        unsigned so = (unsigned)(s * STG_FLOATS) * 4;
        int ko = s * KC;
        #pragma unroll
        for (int it = 0; it < 8; it++) CP16(xdst[it] + so, xsrc[it] + ko);
        #pragma unroll
        for (int q = 0; q < 2; q++)  CP16(wdst[q] + so, wsrc[q] + ko);
        CPCOMMIT();
    }

    const int eq = lane >> 2;           // groupID 0..7
    const int kq = lane & 3;            // threadInGroup 0..3
    const int rbase = wid * 32 + eq;

    #pragma unroll 1
    for (int c = 0; c < NCH; c++) {
        __syncthreads();
        if (c + 2 < NCH) {
            unsigned so = (unsigned)(((c + 2) % STAGES) * STG_FLOATS) * 4;
            int ko = (c + 2) * KC;
            #pragma unroll
            for (int it = 0; it < 8; it++) CP16(xdst[it] + so, xsrc[it] + ko);
            #pragma unroll
            for (int q = 0; q < 2; q++)  CP16(wdst[q] + so, wsrc[q] + ko);
        }
        CPCOMMIT();
        CPWAIT2();
        __syncthreads();

        const float* sx = sm + (c % STAGES) * STG_FLOATS;
        const float* sw = sx + WOFF;

        #pragma unroll
        for (int s = 0; s < 2; s++) {          // two k16 steps per chunk
            const int kl = s * 16 + kq * 2;
            unsigned Ah[2][4], Am[2][4];
            #pragma unroll
            for (int mt = 0; mt < 2; mt++) {
                int r = rbase + mt * 16;
                pairsplit(sx + r * XSTR + kl,           Ah[mt][0], Am[mt][0]);
                pairsplit(sx + (r + 8) * XSTR + kl,     Ah[mt][1], Am[mt][1]);
                pairsplit(sx + r * XSTR + kl + 8,       Ah[mt][2], Am[mt][2]);
                pairsplit(sx + (r + 8) * XSTR + kl + 8, Ah[mt][3], Am[mt][3]);
            }
            unsigned Bh[8][2], Bm[8][2];
            #pragma unroll
            for (int nt = 0; nt < 8; nt++) {
                int e = nt * 8 + eq;
                pairsplitW(sw + e * XSTR + kl,     Bh[nt][0], Bm[nt][0]);
                pairsplitW(sw + e * XSTR + kl + 8, Bh[nt][1], Bm[nt][1]);
            }
            #pragma unroll
            for (int mt = 0; mt < 2; mt++)
                #pragma unroll
                for (int nt = 0; nt < 8; nt++) {
                    mma_f16(acc[mt][nt], Ah[mt], Bh[nt]);
                    mma_f16(acc[mt][nt], Ah[mt], Bm[nt]);
                    mma_f16(acc[mt][nt], Am[mt], Bh[nt]);
                }
        }
    }

    // ---- fp32 partials (still x64-scaled; epilogue unscales the softmax)
    #pragma unroll
    for (int mt = 0; mt < 2; mt++) {
        int row = tok0 + rbase + mt * 16;
        float* d0 = g_partial + ((size_t)ks * T + row) * NE;
        float* d8 = d0 + (size_t)8 * NE;
        #pragma unroll
        for (int nt = 0; nt < 8; nt++) {
            int col = nt * 8 + kq * 2;
            *(float2*)(d0 + col) = make_float2(acc[mt][nt][0], acc[mt][nt][1]);
            *(float2*)(d8 + col) = make_float2(acc[mt][nt][2], acc[mt][nt][3]);
        }
    }
}

// ---------------- reduce + top-2 + softmax ----------------
__global__ __launch_bounds__(256) void moe_top2_kernel(float* __restrict__ out,
                                                       int T, int write_map) {
    const int lane = threadIdx.x & 31;
    const int t = blockIdx.x * 8 + (threadIdx.x >> 5);
    float a = 0.f, bv = 0.f;
    #pragma unroll
    for (int ksi = 0; ksi < KSPL; ksi++) {
        const float* p = g_partial + ((size_t)ksi * T + t) * NE;
        a += p[lane];
        bv += p[lane + 32];
    }

    float v1, v2; int i1, i2;
    if (bv > a) { v1 = bv; i1 = lane + 32; v2 = a; i2 = lane; }
    else        { v1 = a;  i1 = lane;      v2 = bv; i2 = lane + 32; }

    #pragma unroll
    for (int s = 16; s >= 1; s >>= 1) {
        float ov1 = __shfl_xor_sync(0xffffffffu, v1, s);
        int   oi1 = __shfl_xor_sync(0xffffffffu, i1, s);
        float ov2 = __shfl_xor_sync(0xffffffffu, v2, s);
        int   oi2 = __shfl_xor_sync(0xffffffffu, i2, s);
        bool ob = (ov1 > v1) || (ov1 == v1 && oi1 < i1);   // jax tie-break
        float nv1 = ob ? ov1 : v1;  int ni1 = ob ? oi1 : i1;
        float cv  = ob ? v1  : ov1; int ci  = ob ? i1  : oi1;
        float sv  = ob ? ov2 : v2;  int si  = ob ? oi2 : i2;
        bool b2 = (cv > sv) || (cv == sv && ci < si);
        v2 = b2 ? cv : sv; i2 = b2 ? ci : si;
        v1 = nv1; i1 = ni1;
    }
    // logits carry the exact x64 W scale; undo on the difference (exact)
    float ex = expf((v2 - v1) * 0.015625f);   // <= 1, stable
    float inv = 1.f / (1.f + ex);
    float pp1 = inv, pp2 = ex * inv;

    float* probs = out + (size_t)t * NE;
    probs[lane]      = (lane == i1) ? pp1 : ((lane == i2) ? pp2 : 0.f);
    probs[lane + 32] = (lane + 32 == i1) ? pp1 : ((lane + 32 == i2) ? pp2 : 0.f);
    if (write_map) {
        float* rmap = out + (size_t)T * NE + (size_t)t * NE;
        rmap[lane]      = (lane == i1 || lane == i2) ? 1.f : 0.f;
        rmap[lane + 32] = (lane + 32 == i1 || lane + 32 == i2) ? 1.f : 0.f;
    }
}

extern "C" void kernel_launch(void* const* d_in, const int* in_sizes, int n_in,
                              void* d_out, int out_size) {
    const float* x = (const float*)d_in[0];   // [2048,4,4096] fp32
    const float* w = (const float*)d_in[1];   // [64,4096] fp32
    float* out = (float*)d_out;
    int T = in_sizes[0] / HID;                // 8192
    int write_map = (out_size >= 2 * T * NE) ? 1 : 0;

    static int smem_set = 0;
    if (!smem_set) {
        cudaFuncSetAttribute(moe_gemm_kernel,
                             cudaFuncAttributeMaxDynamicSharedMemorySize, SMEM_BYTES);
        smem_set = 1;
    }
    dim3 grid(T / TM, KSPL);
    moe_gemm_kernel<<<grid, NT, SMEM_BYTES>>>(x, w, T);
    moe_top2_kernel<<<T / 8, 256>>>(out, T, write_map);
}

// round 7
// speedup vs baseline: 3.6434x; 1.1328x over previous
#include <cuda_runtime.h>
#include <cuda_fp16.h>
#include <math.h>

// MoE router via mma.sync m16n8k16 fp16 2-plane split (3 products):
//   logits = x[T,4096] @ W[64,4096]^T, fp32 accumulate.
//   x = xh + xm (exact residual); W*64 likewise (exact scale, undone at softmax).
// R7: W pre-split once into interleaved [h2,m2] fp16 pairs (no per-warp B
// conversion); 160B smem row stride for conflict-floor LDS.64 on A and B.

#define HID  4096
#define NE   64
#define TM   256
#define KC   32
#define KSPL 4
#define KPER (HID / KSPL)         // 1024
#define NCH  (KPER / KC)          // 32
#define NT   256
#define STAGES 3
#define XSTR 40                   // A row stride in floats (160B)
#define WOFFB (TM * XSTR * 4)     // 40960 bytes: A stage size
#define WROWB 160                 // B row stride bytes (20 uint2)
#define STG_BYTES (WOFFB + NE * WROWB)       // 51200
#define SMEM_BYTES (STAGES * STG_BYTES)      // 153600

static __device__ unsigned g_wp[NE * HID];             // [e][pair][h2|m2] 1MB
static __device__ float g_partial[KSPL * 8192 * NE];   // 8 MB

__device__ __forceinline__ unsigned smem_u32(const void* p) {
    unsigned r;
    asm("{ .reg .u64 t; cvta.to.shared.u64 t, %1; cvt.u32.u64 %0, t; }"
        : "=r"(r) : "l"(p));
    return r;
}
// split a float2 into fp16 hi plane + exact-residual fp16 mid plane
__device__ __forceinline__ void pairsplit(const float* p, unsigned& h, unsigned& m) {
    float2 v = *(const float2*)p;
    __half2 hh = __float22half2_rn(v);
    float2 hb = __half22float2(hh);
    __half2 mm = __float22half2_rn(make_float2(v.x - hb.x, v.y - hb.y));
    h = *(unsigned*)&hh;
    m = *(unsigned*)&mm;
}
__device__ __forceinline__ void mma_f16(float* c, const unsigned* a, const unsigned* b) {
    asm volatile(
        "mma.sync.aligned.m16n8k16.row.col.f32.f16.f16.f32 "
        "{%0,%1,%2,%3},{%4,%5,%6,%7},{%8,%9},{%0,%1,%2,%3};"
        : "+f"(c[0]), "+f"(c[1]), "+f"(c[2]), "+f"(c[3])
        : "r"(a[0]), "r"(a[1]), "r"(a[2]), "r"(a[3]), "r"(b[0]), "r"(b[1]));
}
#define CP16(dst, src) asm volatile("cp.async.cg.shared.global [%0],[%1],16;" :: "r"(dst), "l"(src))
#define CPCOMMIT()     asm volatile("cp.async.commit_group;")
#define CPWAIT2()      asm volatile("cp.async.wait_group %0;" :: "n"(STAGES - 1))

// ---------------- kernel 1: W -> interleaved fp16 planes (x64 scale) --------
__global__ __launch_bounds__(256) void wsplit_kernel(const float* __restrict__ w) {
    int idx = blockIdx.x * 256 + threadIdx.x;          // pair index
    float2 v = ((const float2*)w)[idx];
    v.x *= 64.f; v.y *= 64.f;
    __half2 h = __float22half2_rn(v);
    float2 hb = __half22float2(h);
    __half2 m = __float22half2_rn(make_float2(v.x - hb.x, v.y - hb.y));
    uint2 o;
    o.x = *(unsigned*)&h;
    o.y = *(unsigned*)&m;
    ((uint2*)g_wp)[idx] = o;
}

// ---------------- kernel 2: split-K(4) GEMM, fp32 partials ----------------
__global__ __launch_bounds__(NT) void moe_gemm_kernel(const float* __restrict__ x, int T) {
    extern __shared__ char smc[];
    const unsigned sbase = smem_u32(smc);
    const int tid = threadIdx.x;
    const int wid = tid >> 5;
    const int lane = tid & 31;
    const int tok0 = blockIdx.x * TM;
    const int ks = blockIdx.y;
    const int kbase = ks * KPER;

    // cp.async mapping (chunk-invariant). x: 8 x 16B/thread.
    const float* xsrc[8]; unsigned xdst[8];
    #pragma unroll
    for (int it = 0; it < 8; it++) {
        int u = it * NT + tid, row = u >> 3, c4 = u & 7;
        xsrc[it] = x + (size_t)(tok0 + row) * HID + kbase + c4 * 4;
        xdst[it] = sbase + (unsigned)(row * XSTR + c4 * 4) * 4;
    }
    // W planes: 8KB/chunk = 512 x 16B segs; 2/thread. row=u>>3, j=u&7.
    const char* wsrc[2]; unsigned wdst[2];
    #pragma unroll
    for (int q = 0; q < 2; q++) {
        int u = q * NT + tid, row = u >> 3, j = u & 7;
        wsrc[q] = (const char*)g_wp + ((size_t)row * 2048 + (kbase >> 1)) * 8 + j * 16;
        wdst[q] = sbase + WOFFB + (unsigned)(row * WROWB + j * 16);
    }

    float acc[2][8][4];
    #pragma unroll
    for (int mt = 0; mt < 2; mt++)
        #pragma unroll
        for (int nt = 0; nt < 8; nt++)
            #pragma unroll
            for (int i = 0; i < 4; i++) acc[mt][nt][i] = 0.f;

    // prologue: stages 0,1
    #pragma unroll
    for (int s = 0; s < 2; s++) {
        unsigned so = (unsigned)(s * STG_BYTES);
        #pragma unroll
        for (int it = 0; it < 8; it++) CP16(xdst[it] + so, xsrc[it] + s * KC);
        #pragma unroll
        for (int q = 0; q < 2; q++)  CP16(wdst[q] + so, wsrc[q] + s * (KC * 4));
        CPCOMMIT();
    }

    const int eq = lane >> 2;           // groupID 0..7
    const int kq = lane & 3;            // threadInGroup 0..3
    const int rbase = wid * 32 + eq;

    #pragma unroll 1
    for (int c = 0; c < NCH; c++) {
        __syncthreads();
        if (c + 2 < NCH) {
            unsigned so = (unsigned)(((c + 2) % STAGES) * STG_BYTES);
            #pragma unroll
            for (int it = 0; it < 8; it++) CP16(xdst[it] + so, xsrc[it] + (c + 2) * KC);
            #pragma unroll
            for (int q = 0; q < 2; q++)  CP16(wdst[q] + so, wsrc[q] + (c + 2) * (KC * 4));
        }
        CPCOMMIT();
        CPWAIT2();
        __syncthreads();

        const float* sx = (const float*)(smc + (c % STAGES) * STG_BYTES);
        const uint2* bw = (const uint2*)(smc + (c % STAGES) * STG_BYTES + WOFFB);

        #pragma unroll
        for (int s = 0; s < 2; s++) {          // two k16 steps per chunk
            const int kl = s * 16 + kq * 2;
            unsigned Ah[2][4], Am[2][4];
            #pragma unroll
            for (int mt = 0; mt < 2; mt++) {
                int r = rbase + mt * 16;
                pairsplit(sx + r * XSTR + kl,           Ah[mt][0], Am[mt][0]);
                pairsplit(sx + (r + 8) * XSTR + kl,     Ah[mt][1], Am[mt][1]);
                pairsplit(sx + r * XSTR + kl + 8,       Ah[mt][2], Am[mt][2]);
                pairsplit(sx + (r + 8) * XSTR + kl + 8, Ah[mt][3], Am[mt][3]);
            }
            unsigned Bh[8][2], Bm[8][2];
            #pragma unroll
            for (int nt = 0; nt < 8; nt++) {
                int e = nt * 8 + eq;
                uint2 t0 = bw[e * 20 + s * 8 + kq];
                uint2 t1 = bw[e * 20 + s * 8 + 4 + kq];
                Bh[nt][0] = t0.x; Bm[nt][0] = t0.y;
                Bh[nt][1] = t1.x; Bm[nt][1] = t1.y;
            }
            #pragma unroll
            for (int mt = 0; mt < 2; mt++)
                #pragma unroll
                for (int nt = 0; nt < 8; nt++) {
                    mma_f16(acc[mt][nt], Ah[mt], Bh[nt]);
                    mma_f16(acc[mt][nt], Ah[mt], Bm[nt]);
                    mma_f16(acc[mt][nt], Am[mt], Bh[nt]);
                }
        }
    }

    // ---- fp32 partials (x64-scaled; epilogue unscales inside softmax)
    #pragma unroll
    for (int mt = 0; mt < 2; mt++) {
        int row = tok0 + rbase + mt * 16;
        float* d0 = g_partial + ((size_t)ks * T + row) * NE;
        float* d8 = d0 + (size_t)8 * NE;
        #pragma unroll
        for (int nt = 0; nt < 8; nt++) {
            int col = nt * 8 + kq * 2;
            *(float2*)(d0 + col) = make_float2(acc[mt][nt][0], acc[mt][nt][1]);
            *(float2*)(d8 + col) = make_float2(acc[mt][nt][2], acc[mt][nt][3]);
        }
    }
}

// ---------------- kernel 3: reduce + top-2 + softmax ----------------
__global__ __launch_bounds__(256) void moe_top2_kernel(float* __restrict__ out,
                                                       int T, int write_map) {
    const int lane = threadIdx.x & 31;
    const int t = blockIdx.x * 8 + (threadIdx.x >> 5);
    float a = 0.f, bv = 0.f;
    #pragma unroll
    for (int ksi = 0; ksi < KSPL; ksi++) {
        const float* p = g_partial + ((size_t)ksi * T + t) * NE;
        a += p[lane];
        bv += p[lane + 32];
    }

    float v1, v2; int i1, i2;
    if (bv > a) { v1 = bv; i1 = lane + 32; v2 = a; i2 = lane; }
    else        { v1 = a;  i1 = lane;      v2 = bv; i2 = lane + 32; }

    #pragma unroll
    for (int s = 16; s >= 1; s >>= 1) {
        float ov1 = __shfl_xor_sync(0xffffffffu, v1, s);
        int   oi1 = __shfl_xor_sync(0xffffffffu, i1, s);
        float ov2 = __shfl_xor_sync(0xffffffffu, v2, s);
        int   oi2 = __shfl_xor_sync(0xffffffffu, i2, s);
        bool ob = (ov1 > v1) || (ov1 == v1 && oi1 < i1);   // jax tie-break
        float nv1 = ob ? ov1 : v1;  int ni1 = ob ? oi1 : i1;
        float cv  = ob ? v1  : ov1; int ci  = ob ? i1  : oi1;
        float sv  = ob ? ov2 : v2;  int si  = ob ? oi2 : i2;
        bool b2 = (cv > sv) || (cv == sv && ci < si);
        v2 = b2 ? cv : sv; i2 = b2 ? ci : si;
        v1 = nv1; i1 = ni1;
    }
    // logits carry the exact x64 W scale; undo on the difference (exact)
    float ex = expf((v2 - v1) * 0.015625f);   // <= 1, stable
    float inv = 1.f / (1.f + ex);
    float pp1 = inv, pp2 = ex * inv;

    float* probs = out + (size_t)t * NE;
    probs[lane]      = (lane == i1) ? pp1 : ((lane == i2) ? pp2 : 0.f);
    probs[lane + 32] = (lane + 32 == i1) ? pp1 : ((lane + 32 == i2) ? pp2 : 0.f);
    if (write_map) {
        float* rmap = out + (size_t)T * NE + (size_t)t * NE;
        rmap[lane]      = (lane == i1 || lane == i2) ? 1.f : 0.f;
        rmap[lane + 32] = (lane + 32 == i1 || lane + 32 == i2) ? 1.f : 0.f;
    }
}

extern "C" void kernel_launch(void* const* d_in, const int* in_sizes, int n_in,
                              void* d_out, int out_size) {
    const float* x = (const float*)d_in[0];   // [2048,4,4096] fp32
    const float* w = (const float*)d_in[1];   // [64,4096] fp32
    float* out = (float*)d_out;
    int T = in_sizes[0] / HID;                // 8192
    int write_map = (out_size >= 2 * T * NE) ? 1 : 0;

    static int smem_set = 0;
    if (!smem_set) {
        cudaFuncSetAttribute(moe_gemm_kernel,
                             cudaFuncAttributeMaxDynamicSharedMemorySize, SMEM_BYTES);
        smem_set = 1;
    }
    wsplit_kernel<<<(NE * HID / 2) / 256, 256>>>(w);
    dim3 grid(T / TM, KSPL);
    moe_gemm_kernel<<<grid, NT, SMEM_BYTES>>>(x, T);
    moe_top2_kernel<<<T / 8, 256>>>(out, T, write_map);
}